// round 7
// baseline (speedup 1.0000x reference)
#include <cuda_runtime.h>
#include <cuda_bf16.h>
#include <cstdint>

// ---------------------------------------------------------------------------
// S4Block on GB300:
//   K0: convert B, C to bf16
//   K1: xB = x @ B^T            (bf16 mma.sync, fp32 accum)
//   K2: scan; 8 CTAs x 256 thr, 2 batches/CTA DECOUPLED via named barriers,
//       one thread = one full A row in regs, broadcast LDS.128, no shfl
//   K3: v = states @ C^T + D*x + x      (residual fused into epilogue)
//   K4: y = LN(v) * gamma + beta
// ---------------------------------------------------------------------------

#define BATCH   16
#define SEQ     2048
#define DM      1024
#define DS      128
#define MTOT    (BATCH * SEQ)          // 32768
#define LN_EPS  1e-5f
#define CH      16                     // xB staging chunk (steps)

// Scratch (device globals; no allocation allowed)
__device__ float          g_xB[MTOT * DS];             // 16 MB
__device__ __nv_bfloat16  g_states[MTOT * DS];         // 8 MB
__device__ __nv_bfloat16  g_Bbf[DS * DM];              // 256 KB
__device__ __nv_bfloat16  g_Cbf[DM * DS];              // 256 KB
__device__ float          g_t[(size_t)MTOT * DM];      // 128 MB

// ---------------------------------------------------------------------------
// helpers
// ---------------------------------------------------------------------------
__device__ __forceinline__ float tanh_fast(float x) {
    float y;
    asm("tanh.approx.f32 %0, %1;" : "=f"(y) : "f"(x));
    return y;
}

typedef unsigned long long u64;
__device__ __forceinline__ u64 pack2(float x, float y) {
    u64 r;
    asm("mov.b64 %0, {%1,%2};" : "=l"(r) : "f"(x), "f"(y));
    return r;
}
__device__ __forceinline__ float2 unpack2(u64 v) {
    float2 f;
    asm("mov.b64 {%0,%1}, %2;" : "=f"(f.x), "=f"(f.y) : "l"(v));
    return f;
}
// packed 2xfp32 FMA (FFMA2): acc = a*b + acc
__device__ __forceinline__ void fma2(u64& acc, u64 a, u64 b) {
    asm("fma.rn.f32x2 %0, %1, %2, %3;" : "=l"(acc) : "l"(a), "l"(b), "l"(acc));
}
// packed 2xfp32 ADD
__device__ __forceinline__ u64 add2(u64 a, u64 b) {
    u64 r;
    asm("add.rn.f32x2 %0, %1, %2;" : "=l"(r) : "l"(a), "l"(b));
    return r;
}

// named barrier for a 128-thread (4-warp) group
__device__ __forceinline__ void bar_group(int id) {
    asm volatile("bar.sync %0, 128;" :: "r"(id) : "memory");
}

__device__ __forceinline__ void cp16(void* smem, const void* gmem) {
    uint32_t s = (uint32_t)__cvta_generic_to_shared(smem);
    asm volatile("cp.async.cg.shared.global [%0], [%1], 16;" :: "r"(s), "l"(gmem));
}
__device__ __forceinline__ void cp_commit() {
    asm volatile("cp.async.commit_group;");
}
template <int N>
__device__ __forceinline__ void cp_wait() {
    asm volatile("cp.async.wait_group %0;" :: "n"(N));
}

__device__ __forceinline__ void mma_bf16(float* d,
                                         uint32_t a0, uint32_t a1, uint32_t a2, uint32_t a3,
                                         uint32_t b0, uint32_t b1) {
    asm("mma.sync.aligned.m16n8k16.row.col.f32.bf16.bf16.f32 "
        "{%0,%1,%2,%3}, {%4,%5,%6,%7}, {%8,%9}, {%0,%1,%2,%3};"
        : "+f"(d[0]), "+f"(d[1]), "+f"(d[2]), "+f"(d[3])
        : "r"(a0), "r"(a1), "r"(a2), "r"(a3), "r"(b0), "r"(b1));
}

// Shared-tile MMA over one [128m x 32k] x [128n x 32k] chunk.
#define TPAD 40
__device__ __forceinline__ void mma_tile(const __nv_bfloat16* As,
                                         const __nv_bfloat16* Bs,
                                         float acc[2][8][4]) {
    const int lane = threadIdx.x & 31;
    const int warp = threadIdx.x >> 5;
    const int wm = warp >> 1;
    const int wn = warp & 1;
    const int lr = lane >> 2;
    const int lc = (lane & 3) * 2;
#pragma unroll
    for (int kk = 0; kk < 32; kk += 16) {
        uint32_t a[2][4];
#pragma unroll
        for (int mi = 0; mi < 2; mi++) {
            const __nv_bfloat16* p = As + (wm * 32 + mi * 16 + lr) * TPAD + kk + lc;
            a[mi][0] = *(const uint32_t*)p;
            a[mi][1] = *(const uint32_t*)(p + 8 * TPAD);
            a[mi][2] = *(const uint32_t*)(p + 8);
            a[mi][3] = *(const uint32_t*)(p + 8 * TPAD + 8);
        }
        uint32_t b[8][2];
#pragma unroll
        for (int ni = 0; ni < 8; ni++) {
            const __nv_bfloat16* p = Bs + (wn * 64 + ni * 8 + lr) * TPAD + kk + lc;
            b[ni][0] = *(const uint32_t*)p;
            b[ni][1] = *(const uint32_t*)(p + 8);
        }
#pragma unroll
        for (int mi = 0; mi < 2; mi++)
#pragma unroll
            for (int ni = 0; ni < 8; ni++)
                mma_bf16(acc[mi][ni], a[mi][0], a[mi][1], a[mi][2], a[mi][3],
                         b[ni][0], b[ni][1]);
    }
}

// ---------------------------------------------------------------------------
// K0: convert B, C to bf16
// ---------------------------------------------------------------------------
__global__ void k0_convert(const float* __restrict__ B, const float* __restrict__ C) {
    int idx = blockIdx.x * 256 + threadIdx.x;
    if (idx < DS * DM) g_Bbf[idx] = __float2bfloat16(B[idx]);
    if (idx < DM * DS) g_Cbf[idx] = __float2bfloat16(C[idx]);
}

// ---------------------------------------------------------------------------
// K1: xB = x @ B^T.  Grid: 256 CTAs (m-tiles of 128). N = 128 (one tile).
// ---------------------------------------------------------------------------
__global__ void __launch_bounds__(256) k1_xB(const float* __restrict__ x) {
    __shared__ __nv_bfloat16 As[128 * TPAD];
    __shared__ __nv_bfloat16 Bs[128 * TPAD];
    const int t = threadIdx.x;
    const int m0 = blockIdx.x * 128;

    float acc[2][8][4];
#pragma unroll
    for (int i = 0; i < 2; i++)
#pragma unroll
        for (int j = 0; j < 8; j++)
#pragma unroll
            for (int k = 0; k < 4; k++) acc[i][j][k] = 0.f;

    for (int kt = 0; kt < DM; kt += 32) {
#pragma unroll
        for (int pass = 0; pass < 4; pass++) {
            int r = pass * 32 + (t >> 3);
            int c = (t & 7) * 4;
            float4 v = *(const float4*)(x + (size_t)(m0 + r) * DM + kt + c);
            __nv_bfloat162 p0 = __floats2bfloat162_rn(v.x, v.y);
            __nv_bfloat162 p1 = __floats2bfloat162_rn(v.z, v.w);
            *(__nv_bfloat162*)&As[r * TPAD + c]     = p0;
            *(__nv_bfloat162*)&As[r * TPAD + c + 2] = p1;
        }
        {
            int r = t >> 1;
            int half = t & 1;
            const __nv_bfloat16* src = g_Bbf + r * DM + kt + half * 16;
            uint4 v0 = *(const uint4*)(src);
            uint4 v1 = *(const uint4*)(src + 8);
            *(uint4*)&Bs[r * TPAD + half * 16]     = v0;
            *(uint4*)&Bs[r * TPAD + half * 16 + 8] = v1;
        }
        __syncthreads();
        mma_tile(As, Bs, acc);
        __syncthreads();
    }

    const int lane = t & 31, warp = t >> 5;
    const int wm = warp >> 1, wn = warp & 1;
    const int lr = lane >> 2, lc = (lane & 3) * 2;
#pragma unroll
    for (int mi = 0; mi < 2; mi++)
#pragma unroll
        for (int ni = 0; ni < 8; ni++) {
            int row = m0 + wm * 32 + mi * 16 + lr;
            int col = wn * 64 + ni * 8 + lc;
            float* o0 = g_xB + (size_t)row * DS + col;
            float* o1 = g_xB + (size_t)(row + 8) * DS + col;
            *(float2*)o0 = make_float2(acc[mi][ni][0], acc[mi][ni][1]);
            *(float2*)o1 = make_float2(acc[mi][ni][2], acc[mi][ni][3]);
        }
}

// ---------------------------------------------------------------------------
// K2: recurrence. 8 CTAs x 256 threads; TWO batches per CTA, fully decoupled:
// group g = warps 4g..4g+3 runs batch 2*blockIdx.x+g with its own named
// barrier (bar.sync g+1, 128), own state ping-pong, own xB buffers.
// One thread = one full A row (64 f32x2 regs); state via broadcast LDS.128.
// Per SMSP: 2 warps with independent chains -> issue/latency overlap.
// ---------------------------------------------------------------------------
__global__ void __launch_bounds__(256, 1) k2_scan(const float* __restrict__ A) {
    const int t = threadIdx.x;
    const int g = t >> 7;                  // batch within pair (warp-aligned)
    const int i = t & 127;                 // row / state element
    const int b = blockIdx.x * 2 + g;
    const int barid = g + 1;

    __shared__ float s_sh[2][2][DS];       // [g][pingpong][DS]
    __shared__ float xb_sh[2][2][CH * DS]; // [g][buf][..]  2 x 2 x 8KB

    // A[i][0..127] as 64 packed f32x2 (128 registers)
    u64 a[64];
#pragma unroll
    for (int u = 0; u < 64; u++) {
        float2 v = *(const float2*)(A + i * DS + 2 * u);
        a[u] = pack2(v.x, v.y);
    }

    const float* xb = g_xB + (size_t)b * SEQ * DS;
    __nv_bfloat16* so = g_states + (size_t)b * SEQ * DS;

    // preload chunks 0 and 1 for this group (128 threads x 4 x 16B = 8KB each)
#pragma unroll
    for (int q = 0; q < 4; q++)
        cp16(&xb_sh[g][0][(q * DS + i) * 4], xb + (q * DS + i) * 4);
    cp_commit();
#pragma unroll
    for (int q = 0; q < 4; q++)
        cp16(&xb_sh[g][1][(q * DS + i) * 4], xb + CH * DS + (q * DS + i) * 4);
    cp_commit();

    s_sh[g][0][i] = 0.f;
    s_sh[g][1][i] = 0.f;
    bar_group(barid);

    for (int c = 0; c < SEQ / CH; c++) {
        cp_wait<1>();          // this thread's chunk c resident
        bar_group(barid);      // group-wide visibility

        const float* xbc = xb_sh[g][c & 1];
#pragma unroll 1
        for (int k = 0; k < CH; k++) {
            const int tt = c * CH + k;
            float xbv = xbc[k * DS + i];   // independent of state; issues early
            const ulonglong2* sv = (const ulonglong2*)(s_sh[g][tt & 1]);
            u64 ac0 = 0ull, ac1 = 0ull, ac2 = 0ull, ac3 = 0ull;
            u64 ac4 = 0ull, ac5 = 0ull, ac6 = 0ull, ac7 = 0ull;
#pragma unroll
            for (int u = 0; u < 32; u += 4) {
                ulonglong2 w0 = sv[u + 0];
                ulonglong2 w1 = sv[u + 1];
                ulonglong2 w2 = sv[u + 2];
                ulonglong2 w3 = sv[u + 3];
                fma2(ac0, a[2 * u + 0], w0.x);
                fma2(ac1, a[2 * u + 1], w0.y);
                fma2(ac2, a[2 * u + 2], w1.x);
                fma2(ac3, a[2 * u + 3], w1.y);
                fma2(ac4, a[2 * u + 4], w2.x);
                fma2(ac5, a[2 * u + 5], w2.y);
                fma2(ac6, a[2 * u + 6], w3.x);
                fma2(ac7, a[2 * u + 7], w3.y);
            }
            u64 s0 = add2(add2(ac0, ac1), add2(ac2, ac3));
            u64 s1 = add2(add2(ac4, ac5), add2(ac6, ac7));
            float2 f = unpack2(add2(s0, s1));
            float s = tanh_fast(f.x + f.y + xbv);
            s_sh[g][(tt + 1) & 1][i] = s;
            so[tt * DS + i] = __float2bfloat16(s);
            bar_group(barid);
        }

        // prefetch chunk c+2 into the buffer just consumed
        if (c + 2 < SEQ / CH) {
            const float* src = xb + (size_t)(c + 2) * CH * DS;
#pragma unroll
            for (int q = 0; q < 4; q++)
                cp16(&xb_sh[g][c & 1][(q * DS + i) * 4], src + (q * DS + i) * 4);
        }
        cp_commit();
    }
}

// ---------------------------------------------------------------------------
// K3: v = states @ C^T + D*x + x  -> g_t.  Grid: (256 m-tiles, 8 n-tiles).
// ---------------------------------------------------------------------------
__global__ void __launch_bounds__(256) k3_out(const float* __restrict__ x,
                                              const float* __restrict__ D) {
    __shared__ __nv_bfloat16 As[128 * TPAD];
    __shared__ __nv_bfloat16 Bs[128 * TPAD];
    const int t = threadIdx.x;
    const int m0 = blockIdx.x * 128;
    const int n0 = blockIdx.y * 128;

    float acc[2][8][4];
#pragma unroll
    for (int i = 0; i < 2; i++)
#pragma unroll
        for (int j = 0; j < 8; j++)
#pragma unroll
            for (int k = 0; k < 4; k++) acc[i][j][k] = 0.f;

    for (int kt = 0; kt < DS; kt += 32) {
        {
            int r = t >> 1;
            int half = t & 1;
            const __nv_bfloat16* src = g_states + (size_t)(m0 + r) * DS + kt + half * 16;
            uint4 v0 = *(const uint4*)(src);
            uint4 v1 = *(const uint4*)(src + 8);
            *(uint4*)&As[r * TPAD + half * 16]     = v0;
            *(uint4*)&As[r * TPAD + half * 16 + 8] = v1;
        }
        {
            int r = t >> 1;
            int half = t & 1;
            const __nv_bfloat16* src = g_Cbf + (n0 + r) * DS + kt + half * 16;
            uint4 v0 = *(const uint4*)(src);
            uint4 v1 = *(const uint4*)(src + 8);
            *(uint4*)&Bs[r * TPAD + half * 16]     = v0;
            *(uint4*)&Bs[r * TPAD + half * 16 + 8] = v1;
        }
        __syncthreads();
        mma_tile(As, Bs, acc);
        __syncthreads();
    }

    const int lane = t & 31, warp = t >> 5;
    const int wm = warp >> 1, wn = warp & 1;
    const int lr = lane >> 2, lc = (lane & 3) * 2;
#pragma unroll
    for (int mi = 0; mi < 2; mi++)
#pragma unroll
        for (int ni = 0; ni < 8; ni++) {
            int row = m0 + wm * 32 + mi * 16 + lr;
            int col = n0 + wn * 64 + ni * 8 + lc;
            float2 d2 = *(const float2*)(D + col);
            float2 x0 = *(const float2*)(x + (size_t)row * DM + col);
            float2 x1 = *(const float2*)(x + (size_t)(row + 8) * DM + col);
            float* o0 = g_t + (size_t)row * DM + col;
            float* o1 = g_t + (size_t)(row + 8) * DM + col;
            *(float2*)o0 = make_float2(acc[mi][ni][0] + (d2.x + 1.f) * x0.x,
                                       acc[mi][ni][1] + (d2.y + 1.f) * x0.y);
            *(float2*)o1 = make_float2(acc[mi][ni][2] + (d2.x + 1.f) * x1.x,
                                       acc[mi][ni][3] + (d2.y + 1.f) * x1.y);
        }
}

// ---------------------------------------------------------------------------
// K4: y = LN(v) * gamma + beta.  One CTA (256 thr) per row; v = g_t row.
// ---------------------------------------------------------------------------
__global__ void __launch_bounds__(256) k4_ln(const float* __restrict__ gamma,
                                             const float* __restrict__ beta,
                                             float* __restrict__ y) {
    const int m = blockIdx.x;
    const int t = threadIdx.x;
    const int c = t * 4;

    float4 v = *(const float4*)(g_t + (size_t)m * DM + c);

    float s = v.x + v.y + v.z + v.w;
    float q = v.x * v.x + v.y * v.y + v.z * v.z + v.w * v.w;
#pragma unroll
    for (int o = 16; o > 0; o >>= 1) {
        s += __shfl_xor_sync(0xffffffffu, s, o);
        q += __shfl_xor_sync(0xffffffffu, q, o);
    }
    __shared__ float ss[8], qq[8];
    __shared__ float mu_s, rs_s;
    if ((t & 31) == 0) { ss[t >> 5] = s; qq[t >> 5] = q; }
    __syncthreads();
    if (t == 0) {
        float S = 0.f, Q = 0.f;
#pragma unroll
        for (int w = 0; w < 8; w++) { S += ss[w]; Q += qq[w]; }
        float mu = S * (1.f / DM);
        float var = Q * (1.f / DM) - mu * mu;
        mu_s = mu;
        rs_s = rsqrtf(var + LN_EPS);
    }
    __syncthreads();
    float mu = mu_s, rs = rs_s;

    float4 g4 = *(const float4*)(gamma + c);
    float4 b4 = *(const float4*)(beta + c);
    float4 out;
    out.x = (v.x - mu) * rs * g4.x + b4.x;
    out.y = (v.y - mu) * rs * g4.y + b4.y;
    out.z = (v.z - mu) * rs * g4.z + b4.z;
    out.w = (v.w - mu) * rs * g4.w + b4.w;
    *(float4*)(y + (size_t)m * DM + c) = out;
}

// ---------------------------------------------------------------------------
extern "C" void kernel_launch(void* const* d_in, const int* in_sizes, int n_in,
                              void* d_out, int out_size) {
    const float* x     = (const float*)d_in[0];
    const float* A     = (const float*)d_in[1];
    const float* B     = (const float*)d_in[2];
    const float* C     = (const float*)d_in[3];
    const float* D     = (const float*)d_in[4];
    const float* gamma = (const float*)d_in[5];
    const float* beta  = (const float*)d_in[6];
    float* y = (float*)d_out;

    k0_convert<<<512, 256>>>(B, C);
    k1_xB<<<MTOT / 128, 256>>>(x);
    k2_scan<<<BATCH / 2, 256>>>(A);
    k3_out<<<dim3(MTOT / 128, DM / 128), 256>>>(x, D);
    k4_ln<<<MTOT, 256>>>(gamma, beta, y);
}

// round 9
// speedup vs baseline: 1.3620x; 1.3620x over previous
#include <cuda_runtime.h>
#include <cuda_bf16.h>
#include <cstdint>

// ---------------------------------------------------------------------------
// S4Block on GB300 — single fused pipeline kernel:
//   k0: convert B,C to bf16 + zero progress flags
//   k_fused (grid 148, 1 CTA/SM, all co-resident):
//     CTA 0..15   : scan for batch b (warps 0-3 compute, warps 4-7 helpers)
//     CTA 16..147 : workers: phase1 xB tiles (publish flags) ->
//                   phase2 out tiles + residual + LayerNorm (poll scan progress)
// ---------------------------------------------------------------------------

#define BATCH   16
#define SEQ     2048
#define DM      1024
#define DS      128
#define MTOT    (BATCH * SEQ)
#define LN_EPS  1e-5f
#define CH      16
#define CHDS    (CH * DS)              // 2048 floats per chunk
#define NW      132                    // worker CTAs
#define NTILES  256                    // 16 batches x 16 stiles

// Scratch (device globals; no allocation allowed)
__device__ float          g_xB[MTOT * DS];             // 16 MB
__device__ __nv_bfloat16  g_states[MTOT * DS];         // 8 MB
__device__ __nv_bfloat16  g_Bbf[DS * DM];              // 256 KB
__device__ __nv_bfloat16  g_Cbf[DM * DS];              // 256 KB
__device__ float          g_t[(size_t)MTOT * DM];      // 128 MB
__device__ volatile unsigned g_flag_xb[NTILES];        // [b*16 + stile]
__device__ volatile unsigned g_prog_scan[BATCH];       // chunks completed

// ---------------------------------------------------------------------------
// helpers
// ---------------------------------------------------------------------------
__device__ __forceinline__ float tanh_fast(float x) {
    float y;
    asm("tanh.approx.f32 %0, %1;" : "=f"(y) : "f"(x));
    return y;
}

typedef unsigned long long u64;
__device__ __forceinline__ u64 pack2(float x, float y) {
    u64 r;
    asm("mov.b64 %0, {%1,%2};" : "=l"(r) : "f"(x), "f"(y));
    return r;
}
__device__ __forceinline__ float2 unpack2(u64 v) {
    float2 f;
    asm("mov.b64 {%0,%1}, %2;" : "=f"(f.x), "=f"(f.y) : "l"(v));
    return f;
}
__device__ __forceinline__ void fma2(u64& acc, u64 a, u64 b) {
    asm("fma.rn.f32x2 %0, %1, %2, %3;" : "=l"(acc) : "l"(a), "l"(b), "l"(acc));
}
__device__ __forceinline__ u64 add2(u64 a, u64 b) {
    u64 r;
    asm("add.rn.f32x2 %0, %1, %2;" : "=l"(r) : "l"(a), "l"(b));
    return r;
}

__device__ __forceinline__ void cp16(void* smem, const void* gmem) {
    uint32_t s = (uint32_t)__cvta_generic_to_shared(smem);
    asm volatile("cp.async.cg.shared.global [%0], [%1], 16;" :: "r"(s), "l"(gmem));
}
__device__ __forceinline__ void cp_commit() {
    asm volatile("cp.async.commit_group;");
}
template <int N>
__device__ __forceinline__ void cp_wait() {
    asm volatile("cp.async.wait_group %0;" :: "n"(N));
}

__device__ __forceinline__ void mma_bf16(float* d,
                                         uint32_t a0, uint32_t a1, uint32_t a2, uint32_t a3,
                                         uint32_t b0, uint32_t b1) {
    asm("mma.sync.aligned.m16n8k16.row.col.f32.bf16.bf16.f32 "
        "{%0,%1,%2,%3}, {%4,%5,%6,%7}, {%8,%9}, {%0,%1,%2,%3};"
        : "+f"(d[0]), "+f"(d[1]), "+f"(d[2]), "+f"(d[3])
        : "r"(a0), "r"(a1), "r"(a2), "r"(a3), "r"(b0), "r"(b1));
}

// MMA over [128m x 32k] x [128n x 32k]; RA/RB = row strides (bf16 elements).
template <int RA, int RB>
__device__ __forceinline__ void mma_tile2(const __nv_bfloat16* As,
                                          const __nv_bfloat16* Bs,
                                          float acc[2][8][4]) {
    const int lane = threadIdx.x & 31;
    const int warp = threadIdx.x >> 5;
    const int wm = warp >> 1;
    const int wn = warp & 1;
    const int lr = lane >> 2;
    const int lc = (lane & 3) * 2;
#pragma unroll
    for (int kk = 0; kk < 32; kk += 16) {
        uint32_t a[2][4];
#pragma unroll
        for (int mi = 0; mi < 2; mi++) {
            const __nv_bfloat16* p = As + (wm * 32 + mi * 16 + lr) * RA + kk + lc;
            a[mi][0] = *(const uint32_t*)p;
            a[mi][1] = *(const uint32_t*)(p + 8 * RA);
            a[mi][2] = *(const uint32_t*)(p + 8);
            a[mi][3] = *(const uint32_t*)(p + 8 * RA + 8);
        }
        uint32_t b[8][2];
#pragma unroll
        for (int ni = 0; ni < 8; ni++) {
            const __nv_bfloat16* p = Bs + (wn * 64 + ni * 8 + lr) * RB + kk + lc;
            b[ni][0] = *(const uint32_t*)p;
            b[ni][1] = *(const uint32_t*)(p + 8);
        }
#pragma unroll
        for (int mi = 0; mi < 2; mi++)
#pragma unroll
            for (int ni = 0; ni < 8; ni++)
                mma_bf16(acc[mi][ni], a[mi][0], a[mi][1], a[mi][2], a[mi][3],
                         b[ni][0], b[ni][1]);
    }
}

// ---------------------------------------------------------------------------
// K0: convert B, C to bf16; zero flags
// ---------------------------------------------------------------------------
__global__ void k0_convert(const float* __restrict__ B, const float* __restrict__ C) {
    int idx = blockIdx.x * 256 + threadIdx.x;
    if (idx < DS * DM) g_Bbf[idx] = __float2bfloat16(B[idx]);
    if (idx < DM * DS) g_Cbf[idx] = __float2bfloat16(C[idx]);
    if (blockIdx.x == 0) {
        if (threadIdx.x < NTILES) g_flag_xb[threadIdx.x] = 0;
        if (threadIdx.x < BATCH)  g_prog_scan[threadIdx.x] = 0;
    }
}

// ---------------------------------------------------------------------------
// Fused pipeline kernel
// ---------------------------------------------------------------------------
__global__ void __launch_bounds__(256, 1)
k_fused(const float* __restrict__ x, const float* __restrict__ A,
        const float* __restrict__ D, const float* __restrict__ gamma,
        const float* __restrict__ beta, float* __restrict__ y) {
    __shared__ __align__(16) char sm_u[45056];   // union: scan 17.4K / k1 20.5K / k3 44K
    const int bid = blockIdx.x;
    const int t = threadIdx.x;

    if (bid < BATCH) {
        // ================= SCAN role (batch b) =================
        const int b = bid;
        float* s_sh = (float*)sm_u;              // [2][128]
        float* xbsh = (float*)(sm_u + 1024);     // [2][CHDS]
        const float* xbg = g_xB + (size_t)b * SEQ * DS;
        __nv_bfloat16* so = g_states + (size_t)b * SEQ * DS;

        u64 a[64];
        if (t < DS) {
#pragma unroll
            for (int u = 0; u < 64; u++) {
                float2 v = *(const float2*)(A + t * DS + 2 * u);
                a[u] = pack2(v.x, v.y);
            }
            s_sh[t] = 0.f;                       // s_sh[0][t]
        } else {
            const int j = t - DS;
            while (g_flag_xb[b * 16] == 0) __nanosleep(64);
            __threadfence();
#pragma unroll
            for (int q = 0; q < 4; q++)
                cp16(&xbsh[(q * DS + j) * 4], xbg + (q * DS + j) * 4);
            cp_commit();
#pragma unroll
            for (int q = 0; q < 4; q++)
                cp16(&xbsh[CHDS + (q * DS + j) * 4], xbg + CHDS + (q * DS + j) * 4);
            cp_commit();
        }

        for (int c = 0; c < SEQ / CH; c++) {
            if (t >= DS) cp_wait<1>();
            __syncthreads();
            const float* xbc = xbsh + (c & 1) * CHDS;
#pragma unroll 1
            for (int k = 0; k < CH; k++) {
                const int tt = c * CH + k;
                if (t < DS) {
                    float xbv = xbc[k * DS + t];
                    const ulonglong2* sv = (const ulonglong2*)(s_sh + (tt & 1) * DS);
                    u64 ac0 = 0ull, ac1 = 0ull, ac2 = 0ull, ac3 = 0ull;
                    u64 ac4 = 0ull, ac5 = 0ull, ac6 = 0ull, ac7 = 0ull;
#pragma unroll
                    for (int u = 0; u < 32; u += 4) {
                        ulonglong2 w0 = sv[u + 0];
                        ulonglong2 w1 = sv[u + 1];
                        ulonglong2 w2 = sv[u + 2];
                        ulonglong2 w3 = sv[u + 3];
                        fma2(ac0, a[2 * u + 0], w0.x);
                        fma2(ac1, a[2 * u + 1], w0.y);
                        fma2(ac2, a[2 * u + 2], w1.x);
                        fma2(ac3, a[2 * u + 3], w1.y);
                        fma2(ac4, a[2 * u + 4], w2.x);
                        fma2(ac5, a[2 * u + 5], w2.y);
                        fma2(ac6, a[2 * u + 6], w3.x);
                        fma2(ac7, a[2 * u + 7], w3.y);
                    }
                    u64 s0 = add2(add2(ac0, ac1), add2(ac2, ac3));
                    u64 s1 = add2(add2(ac4, ac5), add2(ac6, ac7));
                    float2 f = unpack2(add2(s0, s1));
                    float s = tanh_fast(f.x + f.y + xbv);
                    s_sh[((tt + 1) & 1) * DS + t] = s;
                } else {
                    const int j = t - DS;
                    if (tt > 0)
                        so[(size_t)(tt - 1) * DS + j] =
                            __float2bfloat16(s_sh[(tt & 1) * DS + j]);
                    if (k == 0 && c > 0) __threadfence();
                    if (k == 1 && c > 0 && t == DS) g_prog_scan[b] = (unsigned)c;
                }
                __syncthreads();
            }
            if (t >= DS) {
                if (c + 2 < SEQ / CH) {
                    const int j = t - DS;
                    if (((c + 2) & 7) == 0) {
                        while (g_flag_xb[b * 16 + ((c + 2) >> 3)] == 0) __nanosleep(64);
                        __threadfence();
                    }
                    const float* src = xbg + (size_t)(c + 2) * CHDS;
#pragma unroll
                    for (int q = 0; q < 4; q++)
                        cp16(&xbsh[(c & 1) * CHDS + (q * DS + j) * 4],
                             src + (q * DS + j) * 4);
                }
                cp_commit();
            }
        }
        // drain last state (step SEQ-1 lives in s_sh[0])
        if (t >= DS) {
            const int j = t - DS;
            so[(size_t)(SEQ - 1) * DS + j] = __float2bfloat16(s_sh[j]);
            __threadfence();
        }
        __syncthreads();
        if (t == DS) g_prog_scan[b] = SEQ / CH;
        return;
    }

    // ================= WORKER role =================
    const int w = bid - BATCH;                   // 0..NW-1

    // ---- phase 1: xB tiles (stile-major order) ----
    {
        __nv_bfloat16* As40 = (__nv_bfloat16*)sm_u;
        __nv_bfloat16* Bs40 = (__nv_bfloat16*)(sm_u + 10240);
        for (int tile = w; tile < NTILES; tile += NW) {
            const int s = tile >> 4, b = tile & 15;
            const int m0 = b * SEQ + s * 128;

            float acc[2][8][4];
#pragma unroll
            for (int i = 0; i < 2; i++)
#pragma unroll
                for (int j = 0; j < 8; j++)
#pragma unroll
                    for (int k = 0; k < 4; k++) acc[i][j][k] = 0.f;

            for (int kt = 0; kt < DM; kt += 32) {
#pragma unroll
                for (int pass = 0; pass < 4; pass++) {
                    int r = pass * 32 + (t >> 3);
                    int c = (t & 7) * 4;
                    float4 v = *(const float4*)(x + (size_t)(m0 + r) * DM + kt + c);
                    __nv_bfloat162 p0 = __floats2bfloat162_rn(v.x, v.y);
                    __nv_bfloat162 p1 = __floats2bfloat162_rn(v.z, v.w);
                    *(__nv_bfloat162*)&As40[r * 40 + c]     = p0;
                    *(__nv_bfloat162*)&As40[r * 40 + c + 2] = p1;
                }
                {
                    int r = t >> 1;
                    int half = t & 1;
                    const __nv_bfloat16* src = g_Bbf + r * DM + kt + half * 16;
                    uint4 v0 = *(const uint4*)(src);
                    uint4 v1 = *(const uint4*)(src + 8);
                    *(uint4*)&Bs40[r * 40 + half * 16]     = v0;
                    *(uint4*)&Bs40[r * 40 + half * 16 + 8] = v1;
                }
                __syncthreads();
                mma_tile2<40, 40>(As40, Bs40, acc);
                __syncthreads();
            }

            const int lane = t & 31, warp = t >> 5;
            const int wm = warp >> 1, wn = warp & 1;
            const int lr = lane >> 2, lc = (lane & 3) * 2;
#pragma unroll
            for (int mi = 0; mi < 2; mi++)
#pragma unroll
                for (int ni = 0; ni < 8; ni++) {
                    int row = m0 + wm * 32 + mi * 16 + lr;
                    int col = wn * 64 + ni * 8 + lc;
                    float* o0 = g_xB + (size_t)row * DS + col;
                    float* o1 = g_xB + (size_t)(row + 8) * DS + col;
                    *(float2*)o0 = make_float2(acc[mi][ni][0], acc[mi][ni][1]);
                    *(float2*)o1 = make_float2(acc[mi][ni][2], acc[mi][ni][3]);
                }
            __threadfence();
            __syncthreads();
            if (t == 0) g_flag_xb[b * 16 + s] = 1;
        }
    }

    // ---- phase 2: out = states@C^T + (D+1)*x, then LayerNorm -> y ----
    {
        __nv_bfloat16* AsF = (__nv_bfloat16*)sm_u;            // 128 x (stride 136)
        __nv_bfloat16* BsC = (__nv_bfloat16*)(sm_u + 34816);  // 128 x (stride 40)
        for (int tile = w; tile < NTILES; tile += NW) {
            const int s = tile >> 4, b = tile & 15;
            const unsigned need = (unsigned)(s + 1) * 8;
            while (g_prog_scan[b] < need) __nanosleep(128);
            __syncthreads();
            __threadfence();
            const int m0 = b * SEQ + s * 128;

            {   // load full states tile [128 x 128] bf16, stride 136
                int r = t >> 1, h = t & 1;
                const uint4* src = (const uint4*)(g_states + (size_t)(m0 + r) * DS + h * 64);
                uint4* dst = (uint4*)(AsF + r * 136 + h * 64);
#pragma unroll
                for (int q = 0; q < 8; q++) dst[q] = src[q];
            }

            for (int nt = 0; nt < 8; nt++) {
                const int n0 = nt * 128;
                float acc[2][8][4];
#pragma unroll
                for (int i = 0; i < 2; i++)
#pragma unroll
                    for (int j = 0; j < 8; j++)
#pragma unroll
                        for (int k = 0; k < 4; k++) acc[i][j][k] = 0.f;

                for (int kt = 0; kt < DS; kt += 32) {
                    {
                        int r = t >> 1, h = t & 1;
                        const __nv_bfloat16* src = g_Cbf + (n0 + r) * DS + kt + h * 16;
                        *(uint4*)&BsC[r * 40 + h * 16]     = *(const uint4*)src;
                        *(uint4*)&BsC[r * 40 + h * 16 + 8] = *(const uint4*)(src + 8);
                    }
                    __syncthreads();
                    mma_tile2<136, 40>(AsF + kt, BsC, acc);
                    __syncthreads();
                }

                const int lane = t & 31, warp = t >> 5;
                const int wm = warp >> 1, wn = warp & 1;
                const int lr = lane >> 2, lc = (lane & 3) * 2;
#pragma unroll
                for (int mi = 0; mi < 2; mi++)
#pragma unroll
                    for (int ni = 0; ni < 8; ni++) {
                        int row = m0 + wm * 32 + mi * 16 + lr;
                        int col = n0 + wn * 64 + ni * 8 + lc;
                        float2 d2 = *(const float2*)(D + col);
                        float2 x0 = *(const float2*)(x + (size_t)row * DM + col);
                        float2 x1 = *(const float2*)(x + (size_t)(row + 8) * DM + col);
                        float* o0 = g_t + (size_t)row * DM + col;
                        float* o1 = g_t + (size_t)(row + 8) * DM + col;
                        *(float2*)o0 = make_float2(acc[mi][ni][0] + (d2.x + 1.f) * x0.x,
                                                   acc[mi][ni][1] + (d2.y + 1.f) * x0.y);
                        *(float2*)o1 = make_float2(acc[mi][ni][2] + (d2.x + 1.f) * x1.x,
                                                   acc[mi][ni][3] + (d2.y + 1.f) * x1.y);
                    }
            }
            __syncthreads();   // own-CTA g_t writes visible block-wide

            // LayerNorm: one warp per row, 16 rows/warp
            const int wi = t >> 5, lane = t & 31;
            for (int r = wi; r < 128; r += 8) {
                const float* row = g_t + (size_t)(m0 + r) * DM;
                float ssum = 0.f, q2 = 0.f;
                float4 vb[8];
#pragma unroll
                for (int it = 0; it < 8; it++) {
                    float4 v = *(const float4*)(row + it * 128 + lane * 4);
                    vb[it] = v;
                    ssum += v.x + v.y + v.z + v.w;
                    q2 += v.x * v.x + v.y * v.y + v.z * v.z + v.w * v.w;
                }
#pragma unroll
                for (int o = 16; o > 0; o >>= 1) {
                    ssum += __shfl_xor_sync(0xffffffffu, ssum, o);
                    q2   += __shfl_xor_sync(0xffffffffu, q2, o);
                }
                float mu = ssum * (1.f / DM);
                float rs = rsqrtf(q2 * (1.f / DM) - mu * mu + LN_EPS);
                float* yrow = y + (size_t)(m0 + r) * DM;
#pragma unroll
                for (int it = 0; it < 8; it++) {
                    float4 g4 = *(const float4*)(gamma + it * 128 + lane * 4);
                    float4 b4 = *(const float4*)(beta + it * 128 + lane * 4);
                    float4 o;
                    o.x = (vb[it].x - mu) * rs * g4.x + b4.x;
                    o.y = (vb[it].y - mu) * rs * g4.y + b4.y;
                    o.z = (vb[it].z - mu) * rs * g4.z + b4.z;
                    o.w = (vb[it].w - mu) * rs * g4.w + b4.w;
                    *(float4*)(yrow + it * 128 + lane * 4) = o;
                }
            }
            __syncthreads();   // before next tile overwrites AsF
        }
    }
}

// ---------------------------------------------------------------------------
extern "C" void kernel_launch(void* const* d_in, const int* in_sizes, int n_in,
                              void* d_out, int out_size) {
    const float* x     = (const float*)d_in[0];
    const float* A     = (const float*)d_in[1];
    const float* B     = (const float*)d_in[2];
    const float* C     = (const float*)d_in[3];
    const float* D     = (const float*)d_in[4];
    const float* gamma = (const float*)d_in[5];
    const float* beta  = (const float*)d_in[6];
    float* y = (float*)d_out;

    k0_convert<<<512, 256>>>(B, C);
    k_fused<<<BATCH + NW, 256>>>(x, A, D, gamma, beta, y);
}